// round 11
// baseline (speedup 1.0000x reference)
#include <cuda_runtime.h>
#include <math.h>
#include <stdint.h>

#define BB 64
#define RR 8192
#define DD 256

#define EPS_NORM 1e-12f
#define EPS_SUM  1e-8f

// ---------------- device scratch (no allocations allowed) ----------------
__device__ float    g_sims[BB * RR];   // cosine sims
__device__ unsigned g_pack[BB];        // packed {count<<9 | arrivals}; self-resetting
__device__ int      g_idx[BB * RR];    // compacted indices (rare path)
__device__ float    g_w[BB * RR];      // compacted normalized weights

__device__ __forceinline__ float sigmoid_acc(float x) {
    return 1.0f / (1.0f + expf(-x));
}

__device__ __forceinline__ int clip_q(long long qq) {
    return (int)(qq < 0 ? 0 : (qq > (RR - 1) ? (RR - 1) : qq));
}

// 256-bit global load/store (sm_100+), streaming (.cs)
__device__ __forceinline__ void ldg256_cs(const float* p, float r[8]) {
    asm("ld.global.cs.v8.f32 {%0,%1,%2,%3,%4,%5,%6,%7}, [%8];"
        : "=f"(r[0]), "=f"(r[1]), "=f"(r[2]), "=f"(r[3]),
          "=f"(r[4]), "=f"(r[5]), "=f"(r[6]), "=f"(r[7])
        : "l"(p));
}
__device__ __forceinline__ void stg256_cs(float* p, const float r[8]) {
    asm volatile("st.global.cs.v8.f32 [%0], {%1,%2,%3,%4,%5,%6,%7,%8};"
        :: "l"(p),
           "f"(r[0]), "f"(r[1]), "f"(r[2]), "f"(r[3]),
           "f"(r[4]), "f"(r[5]), "f"(r[6]), "f"(r[7])
        : "memory");
}

// ---------------- single kernel: v8 hot loop + reg-capped inline tail --------
// Grid = BB*256 blocks, 256 threads (8 warps), 4 rows/warp, double-buffered.
// __launch_bounds__(256, 6): <=42 regs -> 6 blocks/SM (best measured residency).
__global__ void __launch_bounds__(256, 6) kF(const float* __restrict__ in,
                                             float* __restrict__ out,
                                             const long long* __restrict__ qrels,
                                             const float* __restrict__ thrp,
                                             const float* __restrict__ strp,
                                             const float* __restrict__ scalep,
                                             const float* __restrict__ tempp)
{
    __shared__ float s_qn[DD];
    __shared__ float s_red[8];
    __shared__ int   s_icnt[8];
    __shared__ unsigned s_old;

    const int t    = threadIdx.x;
    const int warp = t >> 5;
    const int lane = t & 31;
    const int b = blockIdx.x >> 8;                 // 256 blocks per batch
    const int rowBase = (blockIdx.x & 255) * 32;

    const int q = clip_q(qrels[b]);

    // --- per-block query-row normalization (1 KB from L2, redundant, cheap) ---
    float v = in[((size_t)b * RR + q) * DD + t];
    float s = v * v;
    #pragma unroll
    for (int o = 16; o > 0; o >>= 1) s += __shfl_xor_sync(0xffffffffu, s, o);
    if (lane == 0) s_red[warp] = s;
    __syncthreads();
    if (t < 8) {
        float x = s_red[t];
        #pragma unroll
        for (int o = 4; o > 0; o >>= 1) x += __shfl_xor_sync(0xffu, x, o);
        if (t == 0) s_red[0] = x;
    }
    __syncthreads();
    const float invn = 1.0f / fmaxf(sqrtf(s_red[0]), EPS_NORM);
    s_qn[t] = v * invn;
    __syncthreads();

    // lane's 8 query values (2x LDS.128)
    float qv[8];
    {
        const float4* qn4 = (const float4*)(s_qn + lane * 8);
        float4 qa = qn4[0], qb = qn4[1];
        qv[0]=qa.x; qv[1]=qa.y; qv[2]=qa.z; qv[3]=qa.w;
        qv[4]=qb.x; qv[5]=qb.y; qv[6]=qb.z; qv[7]=qb.w;
    }

    const float thr = sigmoid_acc(thrp[0]);

    // --- streaming hot loop: 4 contiguous rows per warp, v8, double-buffered --
    const int warpRow0 = rowBase + warp * 4;
    const size_t eoff = ((size_t)b * RR + warpRow0) * DD + lane * 8;
    const float* ipf = in  + eoff;
    float*       opf = out + eoff;

    float a[8], n[8];
    ldg256_cs(ipf, a);

    int cnt = 0;
    #pragma unroll
    for (int i = 0; i < 4; i++) {
        if (i < 3) ldg256_cs(ipf + (i + 1) * DD, n);
        stg256_cs(opf + i * DD, a);

        float ss = 0.0f, dp = 0.0f;
        #pragma unroll
        for (int k = 0; k < 8; k++) {
            ss = fmaf(a[k], a[k],  ss);
            dp = fmaf(a[k], qv[k], dp);
        }

        #pragma unroll
        for (int o = 16; o > 0; o >>= 1) {
            ss += __shfl_xor_sync(0xffffffffu, ss, o);
            dp += __shfl_xor_sync(0xffffffffu, dp, o);
        }
        const int row = warpRow0 + i;
        float sim = dp / fmaxf(sqrtf(ss), EPS_NORM);
        sim = (row == q) ? -1.0f : sim;            // all lanes hold full sums
        if (lane == 0) g_sims[(size_t)b * RR + row] = sim;
        cnt += (sim > thr) ? 1 : 0;

        #pragma unroll
        for (int k = 0; k < 8; k++) a[k] = n[k];
    }

    // --- block count + packed arrival atomic (last block runs the tail) ---
    if (lane == 0) s_icnt[warp] = cnt;
    __syncthreads();
    int blkcnt = s_icnt[0] + s_icnt[1] + s_icnt[2] + s_icnt[3]
               + s_icnt[4] + s_icnt[5] + s_icnt[6] + s_icnt[7];

    const bool ownsQ = (q >= rowBase) && (q < rowBase + 32);
    // Fence ONLY when this block's data must be visible to a potential tail.
    if (blkcnt > 0 || ownsQ) __threadfence();
    __syncthreads();

    if (t == 0) s_old = atomicAdd(&g_pack[b], ((unsigned)blkcnt << 9) | 1u);
    __syncthreads();
    const unsigned old = s_old;
    if ((old & 511u) != 255u) return;          // not the last block of batch b

    const int total = (int)(old >> 9) + blkcnt;
    if (t == 0) atomicExch(&g_pack[b], 0u);    // reset for next graph replay
    if (total == 0) return;                    // out row q already == qrep

    // ================= rare path (may spill; executes ~never) ================
    const float strength = sigmoid_acc(strp[0]) * 0.2f;
    const float temp     = fminf(fmaxf(tempp[0], 0.1f), 10.0f);
    const float scale    = scalep[0];
    const float invT     = 1.0f / temp;

    const float* __restrict__ simsB = g_sims + (size_t)b * RR;

    float es = 0.0f, as = 0.0f;
    int   mycnt = 0;
    for (int i = t; i < RR; i += 256) {
        float sv = simsB[i];
        if (sv > thr) {
            float e  = expf(sv * invT);
            float sw = 1.0f / (1.0f + expf(-(sv - thr) * 10.0f));
            es += e;
            as += e * sw * (1.0f + scale * sv);
            mycnt++;
        }
    }
    float ES, AS;
    {
        float x = es, y = as;
        #pragma unroll
        for (int o = 16; o > 0; o >>= 1) {
            x += __shfl_xor_sync(0xffffffffu, x, o);
            y += __shfl_xor_sync(0xffffffffu, y, o);
        }
        __syncthreads();
        if (lane == 0) s_red[warp] = x;
        __syncthreads();
        if (t < 8) {
            float z = s_red[t];
            #pragma unroll
            for (int o = 4; o > 0; o >>= 1) z += __shfl_xor_sync(0xffu, z, o);
            if (t == 0) s_red[0] = z;
        }
        __syncthreads();
        ES = s_red[0];
        __syncthreads();
        if (lane == 0) s_red[warp] = y;
        __syncthreads();
        if (t < 8) {
            float z = s_red[t];
            #pragma unroll
            for (int o = 4; o > 0; o >>= 1) z += __shfl_xor_sync(0xffu, z, o);
            if (t == 0) s_red[0] = z;
        }
        __syncthreads();
        AS = s_red[0];
    }
    const float C = 1.0f / (AS + EPS_SUM * ES);

    int myOff;
    {
        int inc = mycnt;
        #pragma unroll
        for (int o = 1; o < 32; o <<= 1) {
            int y2 = __shfl_up_sync(0xffffffffu, inc, o);
            if (lane >= o) inc += y2;
        }
        __syncthreads();
        if (lane == 31) s_icnt[warp] = inc;
        __syncthreads();
        if (t < 8) {
            int vv = s_icnt[t];
            #pragma unroll
            for (int o = 1; o < 8; o <<= 1) {
                int y2 = __shfl_up_sync(0xffu, vv, o);
                if (t >= o) vv += y2;
            }
            s_icnt[t] = vv;
        }
        __syncthreads();
        int warpBase = (warp == 0) ? 0 : s_icnt[warp - 1];
        myOff = warpBase + inc - mycnt;
    }

    int pos = myOff;
    for (int i = t; i < RR; i += 256) {
        float sv = simsB[i];
        if (sv > thr) {
            float e  = expf(sv * invT);
            float sw = 1.0f / (1.0f + expf(-(sv - thr) * 10.0f));
            g_idx[(size_t)b * RR + pos] = i;
            g_w [(size_t)b * RR + pos] = e * sw * (1.0f + scale * sv) * C;
            pos++;
        }
    }
    __syncthreads();
    __threadfence_block();

    float acc = 0.0f;
    for (int i = 0; i < total; i++) {
        int   r = g_idx[(size_t)b * RR + i];
        float w = g_w [(size_t)b * RR + i];
        acc += w * in[((size_t)b * RR + r) * DD + t];
    }
    float qv2 = in[((size_t)b * RR + q) * DD + t];
    out[((size_t)b * RR + q) * DD + t] = (1.0f - strength) * qv2 + strength * acc;
}

// ---------------- launch ----------------
extern "C" void kernel_launch(void* const* d_in, const int* in_sizes, int n_in,
                              void* d_out, int out_size)
{
    const float*     reps  = (const float*)d_in[0];
    const long long* qrels = (const long long*)d_in[1];
    const float*     thrp  = (const float*)d_in[2];
    const float*     strp  = (const float*)d_in[3];
    const float*     sclp  = (const float*)d_in[4];
    const float*     tmpp  = (const float*)d_in[5];
    float* out = (float*)d_out;

    kF<<<BB * 256, 256>>>(reps, out, qrels, thrp, strp, sclp, tmpp);
}